// round 4
// baseline (speedup 1.0000x reference)
#include <cuda_runtime.h>
#include <math.h>

#define Bv   4
#define Tv   64
#define Nv   1024
#define Ev   16384
#define Cv   32
#define T1v  62
#define T2v  60

// ---- scratch (static device arrays; referenced ONLY from device code) ----
__device__ float g_h1[Bv * T1v * Nv * Cv];   // after temporal conv 1
__device__ float g_hc[Bv * T1v * Nv * Cv];   // after cheb + relu
__device__ float g_h2[Bv * T2v * Nv * Cv];   // after temporal conv 2
__device__ float g_deg[Nv];
__device__ float g_dinv[Nv];
__device__ int   g_cnt[Nv];
__device__ int   g_rowptr[Nv + 1];
__device__ int   g_offs[Nv];
__device__ int   g_col[Ev];
__device__ float g_val[Ev];
__device__ int   g_is64;

// ------------------------------------------------------------------
// Edge dtype probe: int64 data of small values has zero high words at
// every odd int32 position; int32 random indices cannot be all zero there.
// ------------------------------------------------------------------
__global__ void detect_dtype_kernel(const void* ei) {
    if (threadIdx.x == 0 && blockIdx.x == 0) {
        const int* e32 = (const int*)ei;
        int o = 0;
        for (int i = 1; i < 256; i += 2) o |= e32[i];
        g_is64 = (o == 0) ? 1 : 0;
    }
}

__device__ __forceinline__ void load_edge(const void* ei, int e, int& s, int& d) {
    if (g_is64) {
        const long long* e64 = (const long long*)ei;
        s = (int)e64[e];
        d = (int)e64[Ev + e];
    } else {
        const int* e32 = (const int*)ei;
        s = e32[e];
        d = e32[Ev + e];
    }
}

// ------------------------------------------------------------------
// Edge preprocessing
// ------------------------------------------------------------------
__global__ void prep_zero_kernel() {
    int i = blockIdx.x * blockDim.x + threadIdx.x;
    if (i < Nv) { g_deg[i] = 0.f; g_cnt[i] = 0; }
}

__global__ void prep_edges_kernel(const void* __restrict__ ei,
                                  const float* __restrict__ ew) {
    int e = blockIdx.x * blockDim.x + threadIdx.x;
    if (e >= Ev) return;
    int s, d;
    load_edge(ei, e, s, d);
    if ((unsigned)s >= Nv || (unsigned)d >= Nv) return;   // defensive
    float w = ew[e];
    if (s != d) atomicAdd(&g_deg[s], w);
    atomicAdd(&g_cnt[d], 1);
}

__global__ void prep_dinv_kernel() {
    int i = blockIdx.x * blockDim.x + threadIdx.x;
    if (i < Nv) {
        float dg = g_deg[i];
        g_dinv[i] = (dg > 0.f) ? rsqrtf(dg) : 0.f;
    }
}

// single block, 1024 threads: exclusive scan of g_cnt -> g_rowptr, g_offs
__global__ void prep_scan_kernel() {
    __shared__ int s[Nv];
    int i = threadIdx.x;
    int c = g_cnt[i];
    s[i] = c;
    for (int off = 1; off < Nv; off <<= 1) {
        __syncthreads();
        int v = (i >= off) ? s[i - off] : 0;
        __syncthreads();
        s[i] += v;
    }
    __syncthreads();
    int excl = s[i] - c;
    g_rowptr[i] = excl;
    g_offs[i]   = excl;
    if (i == Nv - 1) g_rowptr[Nv] = s[i];
}

__global__ void prep_scatter_kernel(const void* __restrict__ ei,
                                    const float* __restrict__ ew) {
    int e = blockIdx.x * blockDim.x + threadIdx.x;
    if (e >= Ev) return;
    int s, d;
    load_edge(ei, e, s, d);
    if ((unsigned)s >= Nv || (unsigned)d >= Nv) return;   // defensive
    float w = ew[e];
    float nrm = (s == d) ? 0.f : (-g_dinv[s] * w * g_dinv[d]);
    int pos = atomicAdd(&g_offs[d], 1);
    if ((unsigned)pos < Ev) {                              // defensive
        g_col[pos] = s;
        g_val[pos] = nrm;
    }
}

// ------------------------------------------------------------------
// Temporal gated conv: out[b,t,n,co] =
//   relu( (conv1 + b1) * sigmoid(conv2 + b2) + (conv3 + b3) )
// Tile: 64 n x 32 co per (b,t). 64 threads; thread tile 4n x 8co.
// Gates processed sequentially, reusing a 12KB weight buffer.
// src_sel: 0 -> use x param; 1 -> g_hc.  dst_sel: 0 -> g_h1; 1 -> g_h2.
// ------------------------------------------------------------------
#define XS_STRIDE 65
#define XS_FLOATS (3 * 32 * XS_STRIDE)   // 6240

__global__ __launch_bounds__(64)
void tconv_kernel(const float* __restrict__ xp,
                  const float* __restrict__ w1, const float* __restrict__ b1,
                  const float* __restrict__ w2, const float* __restrict__ b2,
                  const float* __restrict__ w3, const float* __restrict__ b3,
                  int src_sel, int dst_sel, int Tin, int Tout)
{
    __shared__ float ws[3072];        // one gate's weights, bank-swizzled
    __shared__ float xs[XS_FLOATS];   // x tile, transposed, stride 65

    const float* x   = (src_sel == 0) ? xp   : (const float*)g_hc;
    float*       out = (dst_sel == 0) ? g_h1 : g_h2;

    const int tid = threadIdx.x;
    const int n0  = blockIdx.x * 64;
    const int t   = blockIdx.y;
    const int b   = blockIdx.z;

    // load x tile transposed: xs[(k*32+ci)*65 + n] = x[b, t+k, n0+n, ci]
    {
        const float* xb = x + ((long long)(b * Tin + t) * Nv + n0) * Cv;
        for (int idx = tid; idx < 3 * 64 * 32; idx += 64) {
            int k   = idx >> 11;          // /2048
            int rem = idx & 2047;         // n*32 + ci (contiguous in gmem)
            int n   = rem >> 5;
            int ci  = rem & 31;
            xs[(k * 32 + ci) * XS_STRIDE + n] = xb[(long long)k * Nv * Cv + rem];
        }
    }

    const int cg = tid >> 4;     // 0..3 : co group (8 couts)
    const int nt = tid & 15;     // 0..15: n thread
    const int nn = nt * 4;

    float a0[4][8], a1[4][8], a2[4][8];
#pragma unroll
    for (int i = 0; i < 4; ++i)
#pragma unroll
        for (int j = 0; j < 8; ++j) { a0[i][j] = 0.f; a1[i][j] = 0.f; a2[i][j] = 0.f; }

    const float* wsrc[3] = { w1, w2, w3 };
#pragma unroll 1
    for (int g = 0; g < 3; ++g) {
        __syncthreads();   // previous gate's ws reads done (and xs ready on g=0)
        const float* wg = wsrc[g];
        for (int idx = tid; idx < 3072; idx += 64) {
            int co = idx / 96;
            int r  = idx - co * 96;
            ws[r * 32 + ((co + r) & 31)] = wg[idx];
        }
        __syncthreads();

#pragma unroll 2
        for (int ci = 0; ci < 32; ++ci) {
#pragma unroll
            for (int k = 0; k < 3; ++k) {
                const int r = ci * 3 + k;
                float xv[4];
#pragma unroll
                for (int i = 0; i < 4; ++i)
                    xv[i] = xs[(k * 32 + ci) * XS_STRIDE + nn + i];
                float wv[8];
#pragma unroll
                for (int j = 0; j < 8; ++j)
                    wv[j] = ws[r * 32 + ((cg * 8 + j + r) & 31)];
                if (g == 0) {
#pragma unroll
                    for (int j = 0; j < 8; ++j)
#pragma unroll
                        for (int i = 0; i < 4; ++i) a0[i][j] = fmaf(xv[i], wv[j], a0[i][j]);
                } else if (g == 1) {
#pragma unroll
                    for (int j = 0; j < 8; ++j)
#pragma unroll
                        for (int i = 0; i < 4; ++i) a1[i][j] = fmaf(xv[i], wv[j], a1[i][j]);
                } else {
#pragma unroll
                    for (int j = 0; j < 8; ++j)
#pragma unroll
                        for (int i = 0; i < 4; ++i) a2[i][j] = fmaf(xv[i], wv[j], a2[i][j]);
                }
            }
        }
    }
    __syncthreads();   // all xs/ws reads done; reuse xs as staging [n][co] stride 33

#pragma unroll
    for (int j = 0; j < 8; ++j) {
        const int co = cg * 8 + j;
        const float bb1 = b1[co], bb2 = b2[co], bb3 = b3[co];
#pragma unroll
        for (int i = 0; i < 4; ++i) {
            float p = a0[i][j] + bb1;
            float q = a1[i][j] + bb2;
            float r = a2[i][j] + bb3;
            float sg = 1.f / (1.f + __expf(-q));
            float h  = p * sg + r;
            xs[(nn + i) * 33 + co] = (h > 0.f) ? h : 0.f;
        }
    }
    __syncthreads();

    float* ob = out + ((long long)(b * Tout + t) * Nv + n0) * Cv;
    for (int idx = tid; idx < 2048; idx += 64) {
        int n = idx >> 5, co = idx & 31;
        ob[idx] = xs[n * 33 + co];
    }
}

// ------------------------------------------------------------------
// ChebConv K=2 + relu: out = relu(h@W0 + Lh@W1 + bias),
// Lh[n,c] = sum_{e: dst==n} norm[e] * h[src[e], c]
// One warp per node; lane = channel. Reads g_h1, writes g_hc.
// ------------------------------------------------------------------
__global__ __launch_bounds__(256)
void cheb_kernel(const float* __restrict__ W,      // [2,32,32]
                 const float* __restrict__ bias)   // [32]
{
    __shared__ float Ws[2048];
    __shared__ float cb[32];
    __shared__ float sh[8][32];
    __shared__ float sl[8][32];

    const int tid = threadIdx.x;
    for (int i = tid; i < 2048; i += 256) Ws[i] = W[i];
    if (tid < 32) cb[tid] = bias[tid];
    __syncthreads();

    const int w    = tid >> 5;
    const int lane = tid & 31;
    const int b = blockIdx.z, t = blockIdx.y;
    const int n = blockIdx.x * 8 + w;

    const float* hb = g_h1 + (long long)((b * T1v + t) * Nv) * Cv;

    float hv = hb[n * 32 + lane];
    float lh = 0.f;
    const int e0 = g_rowptr[n], e1 = g_rowptr[n + 1];
    for (int e = e0; e < e1; ++e) {
        lh = fmaf(g_val[e], hb[g_col[e] * 32 + lane], lh);
    }
    sh[w][lane] = hv;
    sl[w][lane] = lh;
    __syncwarp();

    float o = cb[lane];
#pragma unroll 8
    for (int c = 0; c < 32; ++c) {
        o = fmaf(sh[w][c], Ws[c * 32 + lane], o);
        o = fmaf(sl[w][c], Ws[1024 + c * 32 + lane], o);
    }
    o = (o > 0.f) ? o : 0.f;
    g_hc[(long long)((b * T1v + t) * Nv + n) * Cv + lane] = o;
}

// ------------------------------------------------------------------
// BatchNorm over (B, T2, C) per node. One block per node. Reads g_h2.
// ------------------------------------------------------------------
__global__ __launch_bounds__(256)
void bn_kernel(const float* __restrict__ gamma,
               const float* __restrict__ beta,
               float* __restrict__ outp)
{
    __shared__ float rs[256], rs2[256];
    __shared__ float s_scale, s_shift;

    const int n   = blockIdx.x;
    const int tid = threadIdx.x;
    const int M   = Bv * T2v * Cv;   // 7680

    float s = 0.f, s2 = 0.f;
    for (int i = tid; i < M; i += 256) {
        int row = i >> 5, c = i & 31;
        float v = g_h2[((long long)row * Nv + n) * 32 + c];
        s += v; s2 += v * v;
    }
    rs[tid] = s; rs2[tid] = s2;
    __syncthreads();
    for (int off = 128; off > 0; off >>= 1) {
        if (tid < off) { rs[tid] += rs[tid + off]; rs2[tid] += rs2[tid + off]; }
        __syncthreads();
    }
    if (tid == 0) {
        float mean = rs[0] / (float)M;
        float var  = rs2[0] / (float)M - mean * mean;
        float rstd = rsqrtf(var + 1e-5f);
        float sc = gamma[n] * rstd;
        s_scale = sc;
        s_shift = beta[n] - mean * sc;
    }
    __syncthreads();
    const float sc = s_scale, sf = s_shift;
    for (int i = tid; i < M; i += 256) {
        int row = i >> 5, c = i & 31;
        long long idx = ((long long)row * Nv + n) * 32 + c;
        outp[idx] = g_h2[idx] * sc + sf;
    }
}

// ------------------------------------------------------------------
extern "C" void kernel_launch(void* const* d_in, const int* in_sizes, int n_in,
                              void* d_out, int out_size)
{
    const float* x   = (const float*)d_in[0];
    const void*  ei  = d_in[1];                 // int32 or int64, probed on device
    const float* ew  = (const float*)d_in[2];
    const float* w11 = (const float*)d_in[3];
    const float* b11 = (const float*)d_in[4];
    const float* w12 = (const float*)d_in[5];
    const float* b12 = (const float*)d_in[6];
    const float* w13 = (const float*)d_in[7];
    const float* b13 = (const float*)d_in[8];
    const float* cW  = (const float*)d_in[9];
    const float* cb  = (const float*)d_in[10];
    const float* w21 = (const float*)d_in[11];
    const float* b21 = (const float*)d_in[12];
    const float* w22 = (const float*)d_in[13];
    const float* b22 = (const float*)d_in[14];
    const float* w23 = (const float*)d_in[15];
    const float* b23 = (const float*)d_in[16];
    const float* gamma = (const float*)d_in[17];
    const float* beta  = (const float*)d_in[18];
    float* out = (float*)d_out;

    // edge preprocessing (CSR by dst)
    detect_dtype_kernel<<<1, 32>>>(ei);
    prep_zero_kernel<<<4, 256>>>();
    prep_edges_kernel<<<Ev / 256, 256>>>(ei, ew);
    prep_dinv_kernel<<<4, 256>>>();
    prep_scan_kernel<<<1, 1024>>>();
    prep_scatter_kernel<<<Ev / 256, 256>>>(ei, ew);

    // temporal conv 1: x -> g_h1   [B,64,N,32] -> [B,62,N,32]
    {
        dim3 grid(Nv / 64, T1v, Bv);
        tconv_kernel<<<grid, 64>>>(x, w11, b11, w12, b12, w13, b13,
                                   0 /*src=x*/, 0 /*dst=g_h1*/, Tv, T1v);
    }
    // cheb conv + relu: g_h1 -> g_hc
    {
        dim3 grid(Nv / 8, T1v, Bv);
        cheb_kernel<<<grid, 256>>>(cW, cb);
    }
    // temporal conv 2: g_hc -> g_h2   [B,62,N,32] -> [B,60,N,32]
    {
        dim3 grid(Nv / 64, T2v, Bv);
        tconv_kernel<<<grid, 64>>>(x /*unused*/, w21, b21, w22, b22, w23, b23,
                                   1 /*src=g_hc*/, 1 /*dst=g_h2*/, T1v, T2v);
    }
    // batch norm per node -> d_out
    bn_kernel<<<Nv, 256>>>(gamma, beta, out);
}

// round 5
// speedup vs baseline: 1.1871x; 1.1871x over previous
#include <cuda_runtime.h>
#include <math.h>

#define Bv   4
#define Tv   64
#define Nv   1024
#define Ev   16384
#define Cv   32
#define T1v  62
#define T2v  60

// ---- scratch (static device arrays; referenced ONLY from device code) ----
__device__ float g_h1[Bv * T1v * Nv * Cv];   // after temporal conv 1
__device__ float g_hc[Bv * T1v * Nv * Cv];   // after cheb + relu
__device__ float g_h2[Bv * T2v * Nv * Cv];   // after temporal conv 2
__device__ float g_wT[2][3][96 * 32];        // transposed weights [layer][gate][r*32+co]
__device__ float g_deg[Nv];
__device__ float g_dinv[Nv];
__device__ int   g_cnt[Nv];
__device__ int   g_rowptr[Nv + 1];
__device__ int   g_offs[Nv];
__device__ int   g_col[Ev];
__device__ float g_val[Ev];
__device__ int   g_is64;

// ---- f32x2 helpers (sm_100+ packed fp32) ----
__device__ __forceinline__ unsigned long long fma2(unsigned long long a,
                                                   unsigned long long b,
                                                   unsigned long long c) {
    unsigned long long d;
    asm("fma.rn.f32x2 %0, %1, %2, %3;" : "=l"(d) : "l"(a), "l"(b), "l"(c));
    return d;
}
__device__ __forceinline__ unsigned long long dup2(float x) {
    unsigned long long d;
    unsigned u = __float_as_uint(x);
    asm("mov.b64 %0, {%1, %1};" : "=l"(d) : "r"(u));
    return d;
}
__device__ __forceinline__ void unpack2(unsigned long long v, float& lo, float& hi) {
    unsigned a, b;
    asm("mov.b64 {%0, %1}, %2;" : "=r"(a), "=r"(b) : "l"(v));
    lo = __uint_as_float(a);
    hi = __uint_as_float(b);
}

// ------------------------------------------------------------------
// Edge dtype probe (int64 vs int32 edge_index)
// ------------------------------------------------------------------
__global__ void detect_dtype_kernel(const void* ei) {
    if (threadIdx.x == 0 && blockIdx.x == 0) {
        const int* e32 = (const int*)ei;
        int o = 0;
        for (int i = 1; i < 256; i += 2) o |= e32[i];
        g_is64 = (o == 0) ? 1 : 0;
    }
}

__device__ __forceinline__ void load_edge(const void* ei, int e, int& s, int& d) {
    if (g_is64) {
        const long long* e64 = (const long long*)ei;
        s = (int)e64[e];
        d = (int)e64[Ev + e];
    } else {
        const int* e32 = (const int*)ei;
        s = e32[e];
        d = e32[Ev + e];
    }
}

// ------------------------------------------------------------------
// Edge preprocessing -> CSR by dst
// ------------------------------------------------------------------
__global__ void prep_zero_kernel() {
    int i = blockIdx.x * blockDim.x + threadIdx.x;
    if (i < Nv) { g_deg[i] = 0.f; g_cnt[i] = 0; }
}

__global__ void prep_edges_kernel(const void* __restrict__ ei,
                                  const float* __restrict__ ew) {
    int e = blockIdx.x * blockDim.x + threadIdx.x;
    if (e >= Ev) return;
    int s, d;
    load_edge(ei, e, s, d);
    if ((unsigned)s >= Nv || (unsigned)d >= Nv) return;
    float w = ew[e];
    if (s != d) atomicAdd(&g_deg[s], w);
    atomicAdd(&g_cnt[d], 1);
}

__global__ void prep_dinv_kernel() {
    int i = blockIdx.x * blockDim.x + threadIdx.x;
    if (i < Nv) {
        float dg = g_deg[i];
        g_dinv[i] = (dg > 0.f) ? rsqrtf(dg) : 0.f;
    }
}

__global__ void prep_scan_kernel() {
    __shared__ int s[Nv];
    int i = threadIdx.x;
    int c = g_cnt[i];
    s[i] = c;
    for (int off = 1; off < Nv; off <<= 1) {
        __syncthreads();
        int v = (i >= off) ? s[i - off] : 0;
        __syncthreads();
        s[i] += v;
    }
    __syncthreads();
    int excl = s[i] - c;
    g_rowptr[i] = excl;
    g_offs[i]   = excl;
    if (i == Nv - 1) g_rowptr[Nv] = s[i];
}

__global__ void prep_scatter_kernel(const void* __restrict__ ei,
                                    const float* __restrict__ ew) {
    int e = blockIdx.x * blockDim.x + threadIdx.x;
    if (e >= Ev) return;
    int s, d;
    load_edge(ei, e, s, d);
    if ((unsigned)s >= Nv || (unsigned)d >= Nv) return;
    float w = ew[e];
    float nrm = (s == d) ? 0.f : (-g_dinv[s] * w * g_dinv[d]);
    int pos = atomicAdd(&g_offs[d], 1);
    if ((unsigned)pos < Ev) {
        g_col[pos] = s;
        g_val[pos] = nrm;
    }
}

// ------------------------------------------------------------------
// Weight transpose: g_wT[layer][g][r*32+co] = w[co*96 + r]
// ------------------------------------------------------------------
__global__ void prep_wt_kernel(const float* __restrict__ w11, const float* __restrict__ w12,
                               const float* __restrict__ w13, const float* __restrict__ w21,
                               const float* __restrict__ w22, const float* __restrict__ w23) {
    int i = blockIdx.x * blockDim.x + threadIdx.x;
    if (i >= 3072) return;
    int r = i >> 5, co = i & 31;
    int s = co * 96 + r;
    g_wT[0][0][i] = w11[s];
    g_wT[0][1][i] = w12[s];
    g_wT[0][2][i] = w13[s];
    g_wT[1][0][i] = w21[s];
    g_wT[1][1][i] = w22[s];
    g_wT[1][2][i] = w23[s];
}

// ------------------------------------------------------------------
// Temporal gated conv with f32x2 packed math.
// out[b,t,n,co] = relu((c1+b1)*sigmoid(c2+b2) + (c3+b3))
// Block: 128 threads, tile 128n x 32co, all 3 gates in one pass.
// Thread: 4 n (consecutive) x 8 co (as 4 f32x2 pairs) x 3 gates = 48 f32x2 accs.
// x tile XOR-swizzled (16B units) for conflict-free transpose store + LDS.128 read.
// Dynamic smem: ws 3*96*32 + xs 3*32*128 floats = 86016 B.
// ------------------------------------------------------------------
#define WS_FLOATS (3 * 96 * 32)    // 9216
#define XS_FLOATS (3 * 32 * 128)   // 12288
#define TC_SMEM   ((WS_FLOATS + XS_FLOATS) * 4)

__global__ __launch_bounds__(128)
void tconv_kernel(const float* __restrict__ xp,
                  const float* __restrict__ b1, const float* __restrict__ b2,
                  const float* __restrict__ b3,
                  int layer, int src_sel, int dst_sel, int Tin, int Tout)
{
    extern __shared__ __align__(16) float sm[];
    float* ws = sm;              // [g][r][co] flat
    float* xs = sm + WS_FLOATS;  // rows of 128 floats, XOR-swizzled 16B units

    const float* x   = (src_sel == 0) ? xp   : (const float*)g_hc;
    float*       out = (dst_sel == 0) ? g_h1 : g_h2;

    const int tid = threadIdx.x;
    const int n0  = blockIdx.x * 128;
    const int t   = blockIdx.y;
    const int b   = blockIdx.z;

    // load weights (flat copy, coalesced, conflict-free)
    {
        const float* wsrc = &g_wT[layer][0][0];
        for (int i = tid; i < WS_FLOATS; i += 128) ws[i] = wsrc[i];
    }
    // load x tile transposed with swizzle:
    // element (rx = k*32+ci, n) stored at xs[rx*128 + ((n>>2)^ci)*4 + (n&3)]
    {
        const float* xb = x + ((long long)(b * Tin + t) * Nv + n0) * Cv;
        for (int idx = tid; idx < XS_FLOATS; idx += 128) {
            int k   = idx >> 12;
            int rem = idx & 4095;        // n*32 + ci (contiguous in gmem)
            int n   = rem >> 5;
            int ci  = rem & 31;
            int rx  = k * 32 + ci;
            xs[rx * 128 + (((n >> 2) ^ ci) << 2) + (n & 3)] =
                xb[(long long)k * Nv * Cv + rem];
        }
    }
    __syncthreads();

    const int cg   = tid >> 5;    // warp id = co group (8 couts)
    const int lane = tid & 31;    // n-unit: n = 4*lane .. 4*lane+3

    unsigned long long acc[3][16];
#pragma unroll
    for (int g = 0; g < 3; ++g)
#pragma unroll
        for (int i = 0; i < 16; ++i) acc[g][i] = 0ull;

#pragma unroll 2
    for (int ci = 0; ci < 32; ++ci) {
#pragma unroll
        for (int k = 0; k < 3; ++k) {
            const int rx = k * 32 + ci;
            const float4 xv4 = *(const float4*)(xs + rx * 128 + ((lane ^ ci) << 2));
            unsigned long long xp2[4];
            xp2[0] = dup2(xv4.x); xp2[1] = dup2(xv4.y);
            xp2[2] = dup2(xv4.z); xp2[3] = dup2(xv4.w);
            const int rw = ci * 3 + k;
            const float* wrow = ws + rw * 32 + cg * 8;
#pragma unroll
            for (int g = 0; g < 3; ++g) {
                const ulonglong2 wab = *(const ulonglong2*)(wrow + g * 3072);
                const ulonglong2 wcd = *(const ulonglong2*)(wrow + g * 3072 + 4);
#pragma unroll
                for (int i = 0; i < 4; ++i) {
                    acc[g][i * 4 + 0] = fma2(xp2[i], wab.x, acc[g][i * 4 + 0]);
                    acc[g][i * 4 + 1] = fma2(xp2[i], wab.y, acc[g][i * 4 + 1]);
                    acc[g][i * 4 + 2] = fma2(xp2[i], wcd.x, acc[g][i * 4 + 2]);
                    acc[g][i * 4 + 3] = fma2(xp2[i], wcd.y, acc[g][i * 4 + 3]);
                }
            }
        }
    }
    __syncthreads();   // all xs/ws reads done; reuse xs as staging [n][33]

    const int nn = lane * 4;
#pragma unroll
    for (int p = 0; p < 4; ++p) {
        const int co0 = cg * 8 + p * 2;
        const float b1a = b1[co0], b1b = b1[co0 + 1];
        const float b2a = b2[co0], b2b = b2[co0 + 1];
        const float b3a = b3[co0], b3b = b3[co0 + 1];
#pragma unroll
        for (int i = 0; i < 4; ++i) {
            float p0, p1, q0, q1, r0, r1;
            unpack2(acc[0][i * 4 + p], p0, p1);
            unpack2(acc[1][i * 4 + p], q0, q1);
            unpack2(acc[2][i * 4 + p], r0, r1);
            p0 += b1a; p1 += b1b;
            q0 += b2a; q1 += b2b;
            r0 += b3a; r1 += b3b;
            float s0 = 1.f / (1.f + __expf(-q0));
            float s1 = 1.f / (1.f + __expf(-q1));
            float h0 = p0 * s0 + r0;
            float h1 = p1 * s1 + r1;
            xs[(nn + i) * 33 + co0]     = (h0 > 0.f) ? h0 : 0.f;
            xs[(nn + i) * 33 + co0 + 1] = (h1 > 0.f) ? h1 : 0.f;
        }
    }
    __syncthreads();

    float* ob = out + ((long long)(b * Tout + t) * Nv + n0) * Cv;
    for (int idx = tid; idx < 4096; idx += 128) {
        ob[idx] = xs[(idx >> 5) * 33 + (idx & 31)];
    }
}

// ------------------------------------------------------------------
// ChebConv K=2 + relu. One warp per node, looping over all t.
// Ws loaded once per block (512 blocks instead of 31744).
// ------------------------------------------------------------------
__global__ __launch_bounds__(256)
void cheb_kernel(const float* __restrict__ W,      // [2,32,32]
                 const float* __restrict__ bias)   // [32]
{
    __shared__ float Ws[2048];
    __shared__ float cb[32];
    __shared__ float sh[8][32];
    __shared__ float sl[8][32];

    const int tid = threadIdx.x;
    for (int i = tid; i < 2048; i += 256) Ws[i] = W[i];
    if (tid < 32) cb[tid] = bias[tid];
    __syncthreads();

    const int w    = tid >> 5;
    const int lane = tid & 31;
    const int b    = blockIdx.y;
    const int n    = blockIdx.x * 8 + w;

    const int e0 = g_rowptr[n], e1 = g_rowptr[n + 1];

    for (int t = 0; t < T1v; ++t) {
        const float* hb = g_h1 + (long long)((b * T1v + t) * Nv) * Cv;

        float hv = hb[n * 32 + lane];
        float lh = 0.f;
        for (int e = e0; e < e1; ++e) {
            lh = fmaf(g_val[e], hb[g_col[e] * 32 + lane], lh);
        }
        sh[w][lane] = hv;
        sl[w][lane] = lh;
        __syncwarp();

        float o = cb[lane];
#pragma unroll 8
        for (int c = 0; c < 32; ++c) {
            o = fmaf(sh[w][c], Ws[c * 32 + lane], o);
            o = fmaf(sl[w][c], Ws[1024 + c * 32 + lane], o);
        }
        o = (o > 0.f) ? o : 0.f;
        g_hc[(long long)((b * T1v + t) * Nv + n) * Cv + lane] = o;
        __syncwarp();
    }
}

// ------------------------------------------------------------------
// BatchNorm over (B, T2, C) per node. One block per node. Reads g_h2.
// ------------------------------------------------------------------
__global__ __launch_bounds__(256)
void bn_kernel(const float* __restrict__ gamma,
               const float* __restrict__ beta,
               float* __restrict__ outp)
{
    __shared__ float rs[256], rs2[256];
    __shared__ float s_scale, s_shift;

    const int n   = blockIdx.x;
    const int tid = threadIdx.x;
    const int M   = Bv * T2v * Cv;   // 7680

    float s = 0.f, s2 = 0.f;
    for (int i = tid; i < M; i += 256) {
        int row = i >> 5, c = i & 31;
        float v = g_h2[((long long)row * Nv + n) * 32 + c];
        s += v; s2 += v * v;
    }
    rs[tid] = s; rs2[tid] = s2;
    __syncthreads();
    for (int off = 128; off > 0; off >>= 1) {
        if (tid < off) { rs[tid] += rs[tid + off]; rs2[tid] += rs2[tid + off]; }
        __syncthreads();
    }
    if (tid == 0) {
        float mean = rs[0] / (float)M;
        float var  = rs2[0] / (float)M - mean * mean;
        float rstd = rsqrtf(var + 1e-5f);
        float sc = gamma[n] * rstd;
        s_scale = sc;
        s_shift = beta[n] - mean * sc;
    }
    __syncthreads();
    const float sc = s_scale, sf = s_shift;
    for (int i = tid; i < M; i += 256) {
        int row = i >> 5, c = i & 31;
        long long idx = ((long long)row * Nv + n) * 32 + c;
        outp[idx] = g_h2[idx] * sc + sf;
    }
}

// ------------------------------------------------------------------
extern "C" void kernel_launch(void* const* d_in, const int* in_sizes, int n_in,
                              void* d_out, int out_size)
{
    const float* x   = (const float*)d_in[0];
    const void*  ei  = d_in[1];
    const float* ew  = (const float*)d_in[2];
    const float* w11 = (const float*)d_in[3];
    const float* b11 = (const float*)d_in[4];
    const float* w12 = (const float*)d_in[5];
    const float* b12 = (const float*)d_in[6];
    const float* w13 = (const float*)d_in[7];
    const float* b13 = (const float*)d_in[8];
    const float* cW  = (const float*)d_in[9];
    const float* cb  = (const float*)d_in[10];
    const float* w21 = (const float*)d_in[11];
    const float* b21 = (const float*)d_in[12];
    const float* w22 = (const float*)d_in[13];
    const float* b22 = (const float*)d_in[14];
    const float* w23 = (const float*)d_in[15];
    const float* b23 = (const float*)d_in[16];
    const float* gamma = (const float*)d_in[17];
    const float* beta  = (const float*)d_in[18];
    float* out = (float*)d_out;

    cudaFuncSetAttribute(tconv_kernel,
                         cudaFuncAttributeMaxDynamicSharedMemorySize, TC_SMEM);

    // edge preprocessing + weight transpose
    detect_dtype_kernel<<<1, 32>>>(ei);
    prep_zero_kernel<<<4, 256>>>();
    prep_edges_kernel<<<Ev / 256, 256>>>(ei, ew);
    prep_wt_kernel<<<12, 256>>>(w11, w12, w13, w21, w22, w23);
    prep_dinv_kernel<<<4, 256>>>();
    prep_scan_kernel<<<1, 1024>>>();
    prep_scatter_kernel<<<Ev / 256, 256>>>(ei, ew);

    // temporal conv 1: x -> g_h1   [B,64,N,32] -> [B,62,N,32]
    {
        dim3 grid(Nv / 128, T1v, Bv);
        tconv_kernel<<<grid, 128, TC_SMEM>>>(x, b11, b12, b13,
                                             0 /*layer*/, 0 /*src=x*/, 0 /*dst=h1*/,
                                             Tv, T1v);
    }
    // cheb conv + relu: g_h1 -> g_hc
    {
        dim3 grid(Nv / 8, Bv);
        cheb_kernel<<<grid, 256>>>(cW, cb);
    }
    // temporal conv 2: g_hc -> g_h2   [B,62,N,32] -> [B,60,N,32]
    {
        dim3 grid(Nv / 128, T2v, Bv);
        tconv_kernel<<<grid, 128, TC_SMEM>>>(x /*unused*/, b21, b22, b23,
                                             1 /*layer*/, 1 /*src=hc*/, 1 /*dst=h2*/,
                                             T1v, T2v);
    }
    // batch norm per node -> d_out
    bn_kernel<<<Nv, 256>>>(gamma, beta, out);
}

// round 6
// speedup vs baseline: 1.3952x; 1.1753x over previous
#include <cuda_runtime.h>
#include <math.h>

#define Bv   4
#define Tv   64
#define Nv   1024
#define Ev   16384
#define Cv   32
#define T1v  62
#define T2v  60

// ---- scratch (static device arrays; referenced ONLY from device code) ----
__device__ float g_h1[Bv * T1v * Nv * Cv];   // after temporal conv 1
__device__ float g_hc[Bv * T1v * Nv * Cv];   // after cheb + relu
__device__ float g_h2[Bv * T2v * Nv * Cv];   // after temporal conv 2
__device__ float g_wT[2][3][96 * 32];        // transposed weights [layer][gate][r*32+co]
__device__ float g_deg[Nv];
__device__ float g_dinv[Nv];
__device__ int   g_cnt[Nv];
__device__ int   g_rowptr[Nv + 1];
__device__ int   g_offs[Nv];
__device__ int   g_col[Ev];
__device__ float g_val[Ev];
__device__ int   g_is64;

// ---- f32x2 helpers (sm_100+ packed fp32) ----
__device__ __forceinline__ unsigned long long fma2(unsigned long long a,
                                                   unsigned long long b,
                                                   unsigned long long c) {
    unsigned long long d;
    asm("fma.rn.f32x2 %0, %1, %2, %3;" : "=l"(d) : "l"(a), "l"(b), "l"(c));
    return d;
}
__device__ __forceinline__ unsigned long long dup2(float x) {
    unsigned long long d;
    unsigned u = __float_as_uint(x);
    asm("mov.b64 %0, {%1, %1};" : "=l"(d) : "r"(u));
    return d;
}
__device__ __forceinline__ void unpack2(unsigned long long v, float& lo, float& hi) {
    unsigned a, b;
    asm("mov.b64 {%0, %1}, %2;" : "=r"(a), "=r"(b) : "l"(v));
    lo = __uint_as_float(a);
    hi = __uint_as_float(b);
}

__device__ __forceinline__ void load_edge(const void* ei, int e, int& s, int& d) {
    if (g_is64) {
        const long long* e64 = (const long long*)ei;
        s = (int)e64[e];
        d = (int)e64[Ev + e];
    } else {
        const int* e32 = (const int*)ei;
        s = e32[e];
        d = e32[Ev + e];
    }
}

// ------------------------------------------------------------------
// Prep kernel 1: zero deg/cnt (blocks 0-3) + dtype probe (block 4).
// int64 edge data of node indices has all-zero high words; int32
// random indices cannot.
// ------------------------------------------------------------------
__global__ void prep_init_kernel(const void* ei) {
    if (blockIdx.x < 4) {
        int i = blockIdx.x * 256 + threadIdx.x;
        g_deg[i] = 0.f;
        g_cnt[i] = 0;
    } else if (threadIdx.x == 0) {
        const int* e32 = (const int*)ei;
        int o = 0;
        for (int i = 1; i < 256; i += 2) o |= e32[i];
        g_is64 = (o == 0) ? 1 : 0;
    }
}

// ------------------------------------------------------------------
// Prep kernel 2: edge degree/count (blocks 0-63) + weight transpose
// (blocks 64-75): g_wT[layer][g][r*32+co] = w[co*96 + r]
// ------------------------------------------------------------------
__global__ void prep_edges_wt_kernel(const void* __restrict__ ei,
                                     const float* __restrict__ ew,
                                     const float* __restrict__ w11, const float* __restrict__ w12,
                                     const float* __restrict__ w13, const float* __restrict__ w21,
                                     const float* __restrict__ w22, const float* __restrict__ w23) {
    if (blockIdx.x < 64) {
        int e = blockIdx.x * 256 + threadIdx.x;
        int s, d;
        load_edge(ei, e, s, d);
        if ((unsigned)s >= Nv || (unsigned)d >= Nv) return;
        float w = ew[e];
        if (s != d) atomicAdd(&g_deg[s], w);
        atomicAdd(&g_cnt[d], 1);
    } else {
        int i = (blockIdx.x - 64) * 256 + threadIdx.x;
        if (i >= 3072) return;
        int r = i >> 5, co = i & 31;
        int s = co * 96 + r;
        g_wT[0][0][i] = w11[s];
        g_wT[0][1][i] = w12[s];
        g_wT[0][2][i] = w13[s];
        g_wT[1][0][i] = w21[s];
        g_wT[1][1][i] = w22[s];
        g_wT[1][2][i] = w23[s];
    }
}

// ------------------------------------------------------------------
// Prep kernel 3 (single block, 1024 threads): dinv + exclusive scan.
// ------------------------------------------------------------------
__global__ void prep_dinv_scan_kernel() {
    __shared__ int s[Nv];
    int i = threadIdx.x;
    float dg = g_deg[i];
    g_dinv[i] = (dg > 0.f) ? rsqrtf(dg) : 0.f;
    int c = g_cnt[i];
    s[i] = c;
    for (int off = 1; off < Nv; off <<= 1) {
        __syncthreads();
        int v = (i >= off) ? s[i - off] : 0;
        __syncthreads();
        s[i] += v;
    }
    __syncthreads();
    int excl = s[i] - c;
    g_rowptr[i] = excl;
    g_offs[i]   = excl;
    if (i == Nv - 1) g_rowptr[Nv] = s[i];
}

// ------------------------------------------------------------------
// Prep kernel 4: CSR scatter.
// ------------------------------------------------------------------
__global__ void prep_scatter_kernel(const void* __restrict__ ei,
                                    const float* __restrict__ ew) {
    int e = blockIdx.x * blockDim.x + threadIdx.x;
    if (e >= Ev) return;
    int s, d;
    load_edge(ei, e, s, d);
    if ((unsigned)s >= Nv || (unsigned)d >= Nv) return;
    float w = ew[e];
    float nrm = (s == d) ? 0.f : (-g_dinv[s] * w * g_dinv[d]);
    int pos = atomicAdd(&g_offs[d], 1);
    if ((unsigned)pos < Ev) {
        g_col[pos] = s;
        g_val[pos] = nrm;
    }
}

// ------------------------------------------------------------------
// Temporal gated conv with f32x2 packed math.
// out[b,t,n,co] = relu((c1+b1)*sigmoid(c2+b2) + (c3+b3))
// Block: 256 threads, tile 128n x 32co, all 3 gates in one pass.
// Warp w (0..7): co group of 4 (2 f32x2 pairs). Lane: 4 consecutive n.
// Thread: 4n x 4co x 3 gates = 24 f32x2 accs (48 regs).
// x tile XOR-swizzled (16B units): conflict-free store + LDS.128 read.
// Dynamic smem: ws 3*96*32 + xs 3*32*128 floats = 86016 B.
// ------------------------------------------------------------------
#define WS_FLOATS (3 * 96 * 32)    // 9216
#define XS_FLOATS (3 * 32 * 128)   // 12288
#define TC_SMEM   ((WS_FLOATS + XS_FLOATS) * 4)

__global__ __launch_bounds__(256)
void tconv_kernel(const float* __restrict__ xp,
                  const float* __restrict__ b1, const float* __restrict__ b2,
                  const float* __restrict__ b3,
                  int layer, int src_sel, int dst_sel, int Tin, int Tout)
{
    extern __shared__ __align__(16) float sm[];
    float* ws = sm;              // [g][r][co] flat
    float* xs = sm + WS_FLOATS;  // rows of 128 floats, XOR-swizzled 16B units

    const float* x   = (src_sel == 0) ? xp   : (const float*)g_hc;
    float*       out = (dst_sel == 0) ? g_h1 : g_h2;

    const int tid = threadIdx.x;
    const int n0  = blockIdx.x * 128;
    const int t   = blockIdx.y;
    const int b   = blockIdx.z;

    // load weights (flat copy, coalesced, conflict-free)
    {
        const float* wsrc = &g_wT[layer][0][0];
        for (int i = tid; i < WS_FLOATS; i += 256) ws[i] = wsrc[i];
    }
    // load x tile transposed with swizzle:
    // element (rx = k*32+ci, n) stored at xs[rx*128 + ((n>>2)^ci)*4 + (n&3)]
    {
        const float* xb = x + ((long long)(b * Tin + t) * Nv + n0) * Cv;
        for (int idx = tid; idx < XS_FLOATS; idx += 256) {
            int k   = idx >> 12;
            int rem = idx & 4095;        // n*32 + ci (contiguous in gmem)
            int n   = rem >> 5;
            int ci  = rem & 31;
            int rx  = k * 32 + ci;
            xs[rx * 128 + (((n >> 2) ^ ci) << 2) + (n & 3)] =
                xb[(long long)k * Nv * Cv + rem];
        }
    }
    __syncthreads();

    const int wg   = tid >> 5;    // warp id = co group (4 couts)
    const int lane = tid & 31;    // n-unit: n = 4*lane .. 4*lane+3

    unsigned long long acc[3][8];
#pragma unroll
    for (int g = 0; g < 3; ++g)
#pragma unroll
        for (int i = 0; i < 8; ++i) acc[g][i] = 0ull;

#pragma unroll 4
    for (int ci = 0; ci < 32; ++ci) {
#pragma unroll
        for (int k = 0; k < 3; ++k) {
            const int rx = k * 32 + ci;
            const float4 xv4 = *(const float4*)(xs + rx * 128 + ((lane ^ ci) << 2));
            unsigned long long xp2[4];
            xp2[0] = dup2(xv4.x); xp2[1] = dup2(xv4.y);
            xp2[2] = dup2(xv4.z); xp2[3] = dup2(xv4.w);
            const int rw = ci * 3 + k;
            const float* wrow = ws + rw * 32 + wg * 4;
#pragma unroll
            for (int g = 0; g < 3; ++g) {
                const ulonglong2 wp = *(const ulonglong2*)(wrow + g * 3072);
#pragma unroll
                for (int i = 0; i < 4; ++i) {
                    acc[g][i * 2 + 0] = fma2(xp2[i], wp.x, acc[g][i * 2 + 0]);
                    acc[g][i * 2 + 1] = fma2(xp2[i], wp.y, acc[g][i * 2 + 1]);
                }
            }
        }
    }
    __syncthreads();   // all xs/ws reads done; reuse xs as staging [n][33]

    const int nn = lane * 4;
#pragma unroll
    for (int p = 0; p < 2; ++p) {
        const int co0 = wg * 4 + p * 2;
        const float b1a = b1[co0], b1b = b1[co0 + 1];
        const float b2a = b2[co0], b2b = b2[co0 + 1];
        const float b3a = b3[co0], b3b = b3[co0 + 1];
#pragma unroll
        for (int i = 0; i < 4; ++i) {
            float p0, p1, q0, q1, r0, r1;
            unpack2(acc[0][i * 2 + p], p0, p1);
            unpack2(acc[1][i * 2 + p], q0, q1);
            unpack2(acc[2][i * 2 + p], r0, r1);
            p0 += b1a; p1 += b1b;
            q0 += b2a; q1 += b2b;
            r0 += b3a; r1 += b3b;
            float s0 = 1.f / (1.f + __expf(-q0));
            float s1 = 1.f / (1.f + __expf(-q1));
            float h0 = p0 * s0 + r0;
            float h1 = p1 * s1 + r1;
            xs[(nn + i) * 33 + co0]     = (h0 > 0.f) ? h0 : 0.f;
            xs[(nn + i) * 33 + co0 + 1] = (h1 > 0.f) ? h1 : 0.f;
        }
    }
    __syncthreads();

    float* ob = out + ((long long)(b * Tout + t) * Nv + n0) * Cv;
    for (int idx = tid; idx < 4096; idx += 256) {
        ob[idx] = xs[(idx >> 5) * 33 + (idx & 31)];
    }
}

// ------------------------------------------------------------------
// ChebConv K=2 + relu. One warp per node, looping over all t.
// ------------------------------------------------------------------
__global__ __launch_bounds__(256)
void cheb_kernel(const float* __restrict__ W,      // [2,32,32]
                 const float* __restrict__ bias)   // [32]
{
    __shared__ float Ws[2048];
    __shared__ float cb[32];
    __shared__ float sh[8][32];
    __shared__ float sl[8][32];

    const int tid = threadIdx.x;
    for (int i = tid; i < 2048; i += 256) Ws[i] = W[i];
    if (tid < 32) cb[tid] = bias[tid];
    __syncthreads();

    const int w    = tid >> 5;
    const int lane = tid & 31;
    const int b    = blockIdx.y;
    const int n    = blockIdx.x * 8 + w;

    const int e0 = g_rowptr[n], e1 = g_rowptr[n + 1];

    for (int t = 0; t < T1v; ++t) {
        const float* hb = g_h1 + (long long)((b * T1v + t) * Nv) * Cv;

        float hv = hb[n * 32 + lane];
        float lh = 0.f;
        for (int e = e0; e < e1; ++e) {
            lh = fmaf(g_val[e], hb[g_col[e] * 32 + lane], lh);
        }
        sh[w][lane] = hv;
        sl[w][lane] = lh;
        __syncwarp();

        float o = cb[lane];
#pragma unroll 8
        for (int c = 0; c < 32; ++c) {
            o = fmaf(sh[w][c], Ws[c * 32 + lane], o);
            o = fmaf(sl[w][c], Ws[1024 + c * 32 + lane], o);
        }
        o = (o > 0.f) ? o : 0.f;
        g_hc[(long long)((b * T1v + t) * Nv + n) * Cv + lane] = o;
        __syncwarp();
    }
}

// ------------------------------------------------------------------
// BatchNorm over (B, T2, C) per node. One block per node. Reads g_h2.
// ------------------------------------------------------------------
__global__ __launch_bounds__(256)
void bn_kernel(const float* __restrict__ gamma,
               const float* __restrict__ beta,
               float* __restrict__ outp)
{
    __shared__ float rs[256], rs2[256];
    __shared__ float s_scale, s_shift;

    const int n   = blockIdx.x;
    const int tid = threadIdx.x;
    const int M   = Bv * T2v * Cv;   // 7680

    float s = 0.f, s2 = 0.f;
    for (int i = tid; i < M; i += 256) {
        int row = i >> 5, c = i & 31;
        float v = g_h2[((long long)row * Nv + n) * 32 + c];
        s += v; s2 += v * v;
    }
    rs[tid] = s; rs2[tid] = s2;
    __syncthreads();
    for (int off = 128; off > 0; off >>= 1) {
        if (tid < off) { rs[tid] += rs[tid + off]; rs2[tid] += rs2[tid + off]; }
        __syncthreads();
    }
    if (tid == 0) {
        float mean = rs[0] / (float)M;
        float var  = rs2[0] / (float)M - mean * mean;
        float rstd = rsqrtf(var + 1e-5f);
        float sc = gamma[n] * rstd;
        s_scale = sc;
        s_shift = beta[n] - mean * sc;
    }
    __syncthreads();
    const float sc = s_scale, sf = s_shift;
    for (int i = tid; i < M; i += 256) {
        int row = i >> 5, c = i & 31;
        long long idx = ((long long)row * Nv + n) * 32 + c;
        outp[idx] = g_h2[idx] * sc + sf;
    }
}

// ------------------------------------------------------------------
extern "C" void kernel_launch(void* const* d_in, const int* in_sizes, int n_in,
                              void* d_out, int out_size)
{
    const float* x   = (const float*)d_in[0];
    const void*  ei  = d_in[1];
    const float* ew  = (const float*)d_in[2];
    const float* w11 = (const float*)d_in[3];
    const float* b11 = (const float*)d_in[4];
    const float* w12 = (const float*)d_in[5];
    const float* b12 = (const float*)d_in[6];
    const float* w13 = (const float*)d_in[7];
    const float* b13 = (const float*)d_in[8];
    const float* cW  = (const float*)d_in[9];
    const float* cb  = (const float*)d_in[10];
    const float* w21 = (const float*)d_in[11];
    const float* b21 = (const float*)d_in[12];
    const float* w22 = (const float*)d_in[13];
    const float* b22 = (const float*)d_in[14];
    const float* w23 = (const float*)d_in[15];
    const float* b23 = (const float*)d_in[16];
    const float* gamma = (const float*)d_in[17];
    const float* beta  = (const float*)d_in[18];
    float* out = (float*)d_out;

    cudaFuncSetAttribute(tconv_kernel,
                         cudaFuncAttributeMaxDynamicSharedMemorySize, TC_SMEM);

    // edge preprocessing + weight transpose (4 launches)
    prep_init_kernel<<<5, 256>>>(ei);
    prep_edges_wt_kernel<<<76, 256>>>(ei, ew, w11, w12, w13, w21, w22, w23);
    prep_dinv_scan_kernel<<<1, 1024>>>();
    prep_scatter_kernel<<<Ev / 256, 256>>>(ei, ew);

    // temporal conv 1: x -> g_h1   [B,64,N,32] -> [B,62,N,32]   (launch #5)
    {
        dim3 grid(Nv / 128, T1v, Bv);
        tconv_kernel<<<grid, 256, TC_SMEM>>>(x, b11, b12, b13,
                                             0 /*layer*/, 0 /*src=x*/, 0 /*dst=h1*/,
                                             Tv, T1v);
    }
    // cheb conv + relu: g_h1 -> g_hc   (launch #6)
    {
        dim3 grid(Nv / 8, Bv);
        cheb_kernel<<<grid, 256>>>(cW, cb);
    }
    // temporal conv 2: g_hc -> g_h2   [B,62,N,32] -> [B,60,N,32]
    {
        dim3 grid(Nv / 128, T2v, Bv);
        tconv_kernel<<<grid, 256, TC_SMEM>>>(x /*unused*/, b21, b22, b23,
                                             1 /*layer*/, 1 /*src=hc*/, 1 /*dst=h2*/,
                                             T1v, T2v);
    }
    // batch norm per node -> d_out
    bn_kernel<<<Nv, 256>>>(gamma, beta, out);
}

// round 7
// speedup vs baseline: 1.6846x; 1.2075x over previous
#include <cuda_runtime.h>
#include <math.h>

#define Bv   4
#define Tv   64
#define Nv   1024
#define Ev   16384
#define Cv   32
#define T1v  62
#define T2v  60

// ---- scratch (static device arrays; referenced ONLY from device code) ----
__device__ float g_h1[Bv * T1v * Nv * Cv];   // after temporal conv 1
__device__ float g_hc[Bv * T1v * Nv * Cv];   // after cheb + relu
__device__ float g_h2[Bv * T2v * Nv * Cv];   // after temporal conv 2
__device__ float g_wT[2][3][96 * 32];        // transposed weights [layer][gate][r*32+co]
__device__ float g_deg[Nv];
__device__ float g_dinv[Nv];
__device__ int   g_cnt[Nv];
__device__ int   g_rowptr[Nv + 1];
__device__ int   g_col[Ev];
__device__ float g_val[Ev];
__device__ int   g_is64;

// ---- f32x2 helpers (sm_100+ packed fp32) ----
__device__ __forceinline__ unsigned long long fma2(unsigned long long a,
                                                   unsigned long long b,
                                                   unsigned long long c) {
    unsigned long long d;
    asm("fma.rn.f32x2 %0, %1, %2, %3;" : "=l"(d) : "l"(a), "l"(b), "l"(c));
    return d;
}
__device__ __forceinline__ unsigned long long dup2(float x) {
    unsigned long long d;
    unsigned u = __float_as_uint(x);
    asm("mov.b64 %0, {%1, %1};" : "=l"(d) : "r"(u));
    return d;
}
__device__ __forceinline__ void unpack2(unsigned long long v, float& lo, float& hi) {
    unsigned a, b;
    asm("mov.b64 {%0, %1}, %2;" : "=r"(a), "=r"(b) : "l"(v));
    lo = __uint_as_float(a);
    hi = __uint_as_float(b);
}

__device__ __forceinline__ void load_edge(const void* ei, int e, int& s, int& d) {
    if (g_is64) {
        const long long* e64 = (const long long*)ei;
        s = (int)e64[e];
        d = (int)e64[Ev + e];
    } else {
        const int* e32 = (const int*)ei;
        s = e32[e];
        d = e32[Ev + e];
    }
}

// ------------------------------------------------------------------
// Prep 1: zero deg/cnt (blocks 0-3) + dtype probe (block 4).
// ------------------------------------------------------------------
__global__ void prep_init_kernel(const void* ei) {
    if (blockIdx.x < 4) {
        int i = blockIdx.x * 256 + threadIdx.x;
        g_deg[i] = 0.f;
        g_cnt[i] = 0;
    } else if (threadIdx.x == 0) {
        const int* e32 = (const int*)ei;
        int o = 0;
        for (int i = 1; i < 256; i += 2) o |= e32[i];
        g_is64 = (o == 0) ? 1 : 0;
    }
}

// ------------------------------------------------------------------
// Prep 2: edge degree/count (blocks 0-63) + weight transpose
// (blocks 64-75): g_wT[layer][g][r*32+co] = w[co*96 + r]
// ------------------------------------------------------------------
__global__ void prep_edges_wt_kernel(const void* __restrict__ ei,
                                     const float* __restrict__ ew,
                                     const float* __restrict__ w11, const float* __restrict__ w12,
                                     const float* __restrict__ w13, const float* __restrict__ w21,
                                     const float* __restrict__ w22, const float* __restrict__ w23) {
    if (blockIdx.x < 64) {
        int e = blockIdx.x * 256 + threadIdx.x;
        int s, d;
        load_edge(ei, e, s, d);
        if ((unsigned)s >= Nv || (unsigned)d >= Nv) return;
        float w = ew[e];
        if (s != d) atomicAdd(&g_deg[s], w);
        atomicAdd(&g_cnt[d], 1);
    } else {
        int i = (blockIdx.x - 64) * 256 + threadIdx.x;
        if (i >= 3072) return;
        int r = i >> 5, co = i & 31;
        int s = co * 96 + r;
        g_wT[0][0][i] = w11[s];
        g_wT[0][1][i] = w12[s];
        g_wT[0][2][i] = w13[s];
        g_wT[1][0][i] = w21[s];
        g_wT[1][1][i] = w22[s];
        g_wT[1][2][i] = w23[s];
    }
}

// ------------------------------------------------------------------
// Prep 3 (single block, 1024 threads): dinv + exclusive scan + scatter.
// ------------------------------------------------------------------
__global__ void prep_finish_kernel(const void* __restrict__ ei,
                                   const float* __restrict__ ew) {
    __shared__ int s[Nv];
    __shared__ int offs[Nv];
    int i = threadIdx.x;
    float dg = g_deg[i];
    g_dinv[i] = (dg > 0.f) ? rsqrtf(dg) : 0.f;
    int c = g_cnt[i];
    s[i] = c;
    for (int off = 1; off < Nv; off <<= 1) {
        __syncthreads();
        int v = (i >= off) ? s[i - off] : 0;
        __syncthreads();
        s[i] += v;
    }
    __syncthreads();
    int excl = s[i] - c;
    g_rowptr[i] = excl;
    offs[i]     = excl;
    if (i == Nv - 1) g_rowptr[Nv] = s[i];
    __syncthreads();

    // scatter (16 edges per thread)
    for (int e = i; e < Ev; e += 1024) {
        int src, dst;
        load_edge(ei, e, src, dst);
        if ((unsigned)src >= Nv || (unsigned)dst >= Nv) continue;
        float w = ew[e];
        float nrm = (src == dst) ? 0.f : (-g_dinv[src] * w * g_dinv[dst]);
        int pos = atomicAdd(&offs[dst], 1);
        if ((unsigned)pos < Ev) {
            g_col[pos] = src;
            g_val[pos] = nrm;
        }
    }
}

// ------------------------------------------------------------------
// Temporal gated conv with f32x2 packed math.
// out[b,t,n,co] = relu((c1+b1)*sigmoid(c2+b2) + (c3+b3))
// Block: 256 threads, tile 128n x 32co, all 3 gates in one pass.
// Warp wg (0..7): co group of 4 (2 f32x2 pairs). Lane: 4 consecutive n.
// Thread: 4n x 4co x 3 gates = 24 f32x2 accs (48 regs).
// ------------------------------------------------------------------
#define WS_FLOATS (3 * 96 * 32)    // 9216
#define XS_FLOATS (3 * 32 * 128)   // 12288
#define TC_SMEM   ((WS_FLOATS + XS_FLOATS) * 4)

__global__ __launch_bounds__(256, 2)
void tconv_kernel(const float* __restrict__ xp,
                  const float* __restrict__ b1, const float* __restrict__ b2,
                  const float* __restrict__ b3,
                  int layer, int src_sel, int dst_sel, int Tin, int Tout)
{
    extern __shared__ __align__(16) float sm[];
    float* ws = sm;              // [g][r][co] flat
    float* xs = sm + WS_FLOATS;  // rows of 128 floats, XOR-swizzled 16B units

    const float* x   = (src_sel == 0) ? xp   : (const float*)g_hc;
    float*       out = (dst_sel == 0) ? g_h1 : g_h2;

    const int tid = threadIdx.x;
    const int n0  = blockIdx.x * 128;
    const int t   = blockIdx.y;
    const int b   = blockIdx.z;

    {
        const float* wsrc = &g_wT[layer][0][0];
        for (int i = tid; i < WS_FLOATS; i += 256) ws[i] = wsrc[i];
    }
    // x tile transposed with swizzle:
    // element (rx = k*32+ci, n) at xs[rx*128 + ((n>>2)^ci)*4 + (n&3)]
    {
        const float* xb = x + ((long long)(b * Tin + t) * Nv + n0) * Cv;
        for (int idx = tid; idx < XS_FLOATS; idx += 256) {
            int k   = idx >> 12;
            int rem = idx & 4095;        // n*32 + ci (contiguous in gmem)
            int n   = rem >> 5;
            int ci  = rem & 31;
            int rx  = k * 32 + ci;
            xs[rx * 128 + (((n >> 2) ^ ci) << 2) + (n & 3)] =
                xb[(long long)k * Nv * Cv + rem];
        }
    }
    __syncthreads();

    const int wg   = tid >> 5;    // warp id = co group (4 couts)
    const int lane = tid & 31;    // n-unit: n = 4*lane .. 4*lane+3

    unsigned long long acc[3][8];
#pragma unroll
    for (int g = 0; g < 3; ++g)
#pragma unroll
        for (int i = 0; i < 8; ++i) acc[g][i] = 0ull;

#pragma unroll 4
    for (int ci = 0; ci < 32; ++ci) {
#pragma unroll
        for (int k = 0; k < 3; ++k) {
            const int rx = k * 32 + ci;
            const float4 xv4 = *(const float4*)(xs + rx * 128 + ((lane ^ ci) << 2));
            unsigned long long xp2[4];
            xp2[0] = dup2(xv4.x); xp2[1] = dup2(xv4.y);
            xp2[2] = dup2(xv4.z); xp2[3] = dup2(xv4.w);
            const int rw = ci * 3 + k;
            const float* wrow = ws + rw * 32 + wg * 4;
#pragma unroll
            for (int g = 0; g < 3; ++g) {
                const ulonglong2 wp = *(const ulonglong2*)(wrow + g * 3072);
#pragma unroll
                for (int i = 0; i < 4; ++i) {
                    acc[g][i * 2 + 0] = fma2(xp2[i], wp.x, acc[g][i * 2 + 0]);
                    acc[g][i * 2 + 1] = fma2(xp2[i], wp.y, acc[g][i * 2 + 1]);
                }
            }
        }
    }
    __syncthreads();   // all xs/ws reads done; reuse xs as staging [n][33]

    const int nn = lane * 4;
#pragma unroll
    for (int p = 0; p < 2; ++p) {
        const int co0 = wg * 4 + p * 2;
        const float b1a = b1[co0], b1b = b1[co0 + 1];
        const float b2a = b2[co0], b2b = b2[co0 + 1];
        const float b3a = b3[co0], b3b = b3[co0 + 1];
#pragma unroll
        for (int i = 0; i < 4; ++i) {
            float p0, p1, q0, q1, r0, r1;
            unpack2(acc[0][i * 2 + p], p0, p1);
            unpack2(acc[1][i * 2 + p], q0, q1);
            unpack2(acc[2][i * 2 + p], r0, r1);
            p0 += b1a; p1 += b1b;
            q0 += b2a; q1 += b2b;
            r0 += b3a; r1 += b3b;
            float s0 = 1.f / (1.f + __expf(-q0));
            float s1 = 1.f / (1.f + __expf(-q1));
            float h0 = p0 * s0 + r0;
            float h1 = p1 * s1 + r1;
            xs[(nn + i) * 33 + co0]     = (h0 > 0.f) ? h0 : 0.f;
            xs[(nn + i) * 33 + co0 + 1] = (h1 > 0.f) ? h1 : 0.f;
        }
    }
    __syncthreads();

    float* ob = out + ((long long)(b * Tout + t) * Nv + n0) * Cv;
    for (int idx = tid; idx < 4096; idx += 256) {
        ob[idx] = xs[(idx >> 5) * 33 + (idx & 31)];
    }
}

// ------------------------------------------------------------------
// ChebConv K=2 + relu. One warp per node, looping over half the t range.
// Edge gather unrolled x4 for MLP.
// ------------------------------------------------------------------
__global__ __launch_bounds__(256)
void cheb_kernel(const float* __restrict__ W,      // [2,32,32]
                 const float* __restrict__ bias)   // [32]
{
    __shared__ float Ws[2048];
    __shared__ float cb[32];
    __shared__ float sh[8][32];
    __shared__ float sl[8][32];

    const int tid = threadIdx.x;
    for (int i = tid; i < 2048; i += 256) Ws[i] = W[i];
    if (tid < 32) cb[tid] = bias[tid];
    __syncthreads();

    const int w     = tid >> 5;
    const int lane  = tid & 31;
    const int thalf = blockIdx.y;      // 0 or 1 -> t in [31*thalf, 31*thalf+31)
    const int b     = blockIdx.z;
    const int n     = blockIdx.x * 8 + w;

    const int e0 = g_rowptr[n], e1 = g_rowptr[n + 1];
    const int t0 = thalf * 31;

    for (int t = t0; t < t0 + 31; ++t) {
        const float* hb = g_h1 + (long long)((b * T1v + t) * Nv) * Cv;

        float hv = hb[n * 32 + lane];
        float lh = 0.f;
        int e = e0;
        for (; e + 4 <= e1; e += 4) {
            int   c0 = g_col[e],     c1 = g_col[e + 1];
            int   c2 = g_col[e + 2], c3 = g_col[e + 3];
            float v0 = g_val[e],     v1 = g_val[e + 1];
            float v2 = g_val[e + 2], v3 = g_val[e + 3];
            float h0 = hb[c0 * 32 + lane];
            float h1 = hb[c1 * 32 + lane];
            float h2 = hb[c2 * 32 + lane];
            float h3 = hb[c3 * 32 + lane];
            lh = fmaf(v0, h0, lh);
            lh = fmaf(v1, h1, lh);
            lh = fmaf(v2, h2, lh);
            lh = fmaf(v3, h3, lh);
        }
        for (; e < e1; ++e) {
            lh = fmaf(g_val[e], hb[g_col[e] * 32 + lane], lh);
        }
        sh[w][lane] = hv;
        sl[w][lane] = lh;
        __syncwarp();

        float o = cb[lane];
#pragma unroll 8
        for (int c = 0; c < 32; ++c) {
            o = fmaf(sh[w][c], Ws[c * 32 + lane], o);
            o = fmaf(sl[w][c], Ws[1024 + c * 32 + lane], o);
        }
        o = (o > 0.f) ? o : 0.f;
        g_hc[(long long)((b * T1v + t) * Nv + n) * Cv + lane] = o;
        __syncwarp();
    }
}

// ------------------------------------------------------------------
// BatchNorm over (B, T2, C) per node. One block per node. Reads g_h2.
// ------------------------------------------------------------------
__global__ __launch_bounds__(256)
void bn_kernel(const float* __restrict__ gamma,
               const float* __restrict__ beta,
               float* __restrict__ outp)
{
    __shared__ float rs[256], rs2[256];
    __shared__ float s_scale, s_shift;

    const int n   = blockIdx.x;
    const int tid = threadIdx.x;
    const int M   = Bv * T2v * Cv;   // 7680

    float s = 0.f, s2 = 0.f;
    for (int i = tid; i < M; i += 256) {
        int row = i >> 5, c = i & 31;
        float v = g_h2[((long long)row * Nv + n) * 32 + c];
        s += v; s2 += v * v;
    }
    rs[tid] = s; rs2[tid] = s2;
    __syncthreads();
    for (int off = 128; off > 0; off >>= 1) {
        if (tid < off) { rs[tid] += rs[tid + off]; rs2[tid] += rs2[tid + off]; }
        __syncthreads();
    }
    if (tid == 0) {
        float mean = rs[0] / (float)M;
        float var  = rs2[0] / (float)M - mean * mean;
        float rstd = rsqrtf(var + 1e-5f);
        float sc = gamma[n] * rstd;
        s_scale = sc;
        s_shift = beta[n] - mean * sc;
    }
    __syncthreads();
    const float sc = s_scale, sf = s_shift;
    for (int i = tid; i < M; i += 256) {
        int row = i >> 5, c = i & 31;
        long long idx = ((long long)row * Nv + n) * 32 + c;
        outp[idx] = g_h2[idx] * sc + sf;
    }
}

// ------------------------------------------------------------------
extern "C" void kernel_launch(void* const* d_in, const int* in_sizes, int n_in,
                              void* d_out, int out_size)
{
    const float* x   = (const float*)d_in[0];
    const void*  ei  = d_in[1];
    const float* ew  = (const float*)d_in[2];
    const float* w11 = (const float*)d_in[3];
    const float* b11 = (const float*)d_in[4];
    const float* w12 = (const float*)d_in[5];
    const float* b12 = (const float*)d_in[6];
    const float* w13 = (const float*)d_in[7];
    const float* b13 = (const float*)d_in[8];
    const float* cW  = (const float*)d_in[9];
    const float* cb  = (const float*)d_in[10];
    const float* w21 = (const float*)d_in[11];
    const float* b21 = (const float*)d_in[12];
    const float* w22 = (const float*)d_in[13];
    const float* b22 = (const float*)d_in[14];
    const float* w23 = (const float*)d_in[15];
    const float* b23 = (const float*)d_in[16];
    const float* gamma = (const float*)d_in[17];
    const float* beta  = (const float*)d_in[18];
    float* out = (float*)d_out;

    cudaFuncSetAttribute(tconv_kernel,
                         cudaFuncAttributeMaxDynamicSharedMemorySize, TC_SMEM);

    // edge preprocessing + weight transpose (3 launches)
    prep_init_kernel<<<5, 256>>>(ei);
    prep_edges_wt_kernel<<<76, 256>>>(ei, ew, w11, w12, w13, w21, w22, w23);
    prep_finish_kernel<<<1, 1024>>>(ei, ew);

    // temporal conv 1: x -> g_h1   (launch #4 -> ncu capture window)
    {
        dim3 grid(Nv / 128, T1v, Bv);
        tconv_kernel<<<grid, 256, TC_SMEM>>>(x, b11, b12, b13,
                                             0, 0, 0, Tv, T1v);
    }
    // cheb conv + relu: g_h1 -> g_hc
    {
        dim3 grid(Nv / 8, 2, Bv);
        cheb_kernel<<<grid, 256>>>(cW, cb);
    }
    // temporal conv 2: g_hc -> g_h2
    {
        dim3 grid(Nv / 128, T2v, Bv);
        tconv_kernel<<<grid, 256, TC_SMEM>>>(x, b21, b22, b23,
                                             1, 1, 1, T1v, T2v);
    }
    // batch norm per node -> d_out
    bn_kernel<<<Nv, 256>>>(gamma, beta, out);
}